// round 12
// baseline (speedup 1.0000x reference)
#include <cuda_runtime.h>
#include <cuda_bf16.h>
#include <cstdint>
#include <math.h>

#define T_STEPS 256
#define INPUT   12288
#define HID     1024
#define GATES   4096

// ---------------- device scratch (no allocations allowed) ----------------
__device__ float              g_xproj[T_STEPS * GATES];  // 4 MB
__device__ unsigned long long g_hp[2][HID];              // {epoch|h} ping-pong

// ---------------- helpers: packed f32x2 FMA (scan) ----------------
__device__ __forceinline__ void ffma2(unsigned long long& d,
                                      unsigned long long a,
                                      unsigned long long b) {
    asm("fma.rn.f32x2 %0, %1, %2, %0;" : "+l"(d) : "l"(a), "l"(b));
}
__device__ __forceinline__ void unpack2(unsigned long long v, float& lo, float& hi) {
    asm("mov.b64 {%0, %1}, %2;" : "=f"(lo), "=f"(hi) : "l"(v));
}

// ---------------- init ----------------
__global__ void init_kernel() {
    int tid = blockIdx.x * blockDim.x + threadIdx.x;
    if (tid < HID) {
        g_hp[0][tid] = 0ULL;
        g_hp[1][tid] = 0ULL;
    }
}

// ---------------- tf32 mma GEMM: x_proj = frames @ W_ih^T + biases ----------------
// CTA tile 128m x 64n, grid (64, 2) = 128 CTAs. 8 warps as 4(m) x 2(n), warp 32x32.
// Both operands read fp32 from GMEM, converted to tf32 at STS time.
#define GK 32                    // fp32 k-columns per chunk
#define NCH (INPUT / GK)         // 384
#define PITCH 36                 // floats per smem row (144 B) -> conflict-free
#define A_MAT_B (128 * PITCH * 4)    // 18432 B
#define B_MAT_B (64 * PITCH * 4)     //  9216 B
#define STAGE_B (A_MAT_B + B_MAT_B)  // 27648
#define GEMM_SMEM (2 * STAGE_B)      // 55296
#define OFF_A 0
#define OFF_B A_MAT_B

__device__ __forceinline__ uint32_t f2tf(float f) {
    uint32_t r;
    asm("cvt.rna.tf32.f32 %0, %1;" : "=r"(r) : "f"(f));
    return r;
}
__device__ __forceinline__ void mma_tf32(float c[4], const uint32_t a[4],
                                         const uint32_t b[2]) {
    asm volatile(
        "mma.sync.aligned.m16n8k8.row.col.f32.tf32.tf32.f32 "
        "{%0,%1,%2,%3}, {%4,%5,%6,%7}, {%8,%9}, {%0,%1,%2,%3};"
        : "+f"(c[0]), "+f"(c[1]), "+f"(c[2]), "+f"(c[3])
        : "r"(a[0]), "r"(a[1]), "r"(a[2]), "r"(a[3]), "r"(b[0]), "r"(b[1]));
}

__global__ __launch_bounds__(256, 1)
void gemm_tf32_kernel(const float* __restrict__ A,
                      const float* __restrict__ W,
                      const float* __restrict__ b_ih,
                      const float* __restrict__ b_hh) {
    extern __shared__ float smem[];
    const int tid  = threadIdx.x;
    const int warp = tid >> 5;
    const int lane = tid & 31;
    const int g    = lane >> 2;
    const int tg   = lane & 3;
    const int n0   = blockIdx.x * 64;
    const int m0   = blockIdx.y * 128;
    const int wm   = (warp & 3) * 32;
    const int wn   = (warp >> 2) * 32;

    float acc[2][4][4];
#pragma unroll
    for (int i = 0; i < 2; i++)
#pragma unroll
        for (int j = 0; j < 4; j++)
#pragma unroll
            for (int q = 0; q < 4; q++) acc[i][j][q] = 0.f;

    // global-load mapping: A 1024 float4/chunk -> 4/thread; B 512 -> 2/thread
    int arow[4], ac4[4], brow[2], bc4[2];
#pragma unroll
    for (int p = 0; p < 4; p++) { int idx = tid + p * 256; arow[p] = idx >> 3; ac4[p] = idx & 7; }
#pragma unroll
    for (int p = 0; p < 2; p++) { int idx = tid + p * 256; brow[p] = idx >> 3; bc4[p] = idx & 7; }

    float4 pA[4], pB[2];

    // ---- prologue: LDG chunk 0, cvt, STS -> stage 0 ----
#pragma unroll
    for (int p = 0; p < 4; p++)
        pA[p] = *(const float4*)(A + (size_t)(m0 + arow[p]) * INPUT + ac4[p] * 4);
#pragma unroll
    for (int p = 0; p < 2; p++)
        pB[p] = *(const float4*)(W + (size_t)(n0 + brow[p]) * INPUT + bc4[p] * 4);
    {
        uint32_t* st = (uint32_t*)smem;
#pragma unroll
        for (int p = 0; p < 4; p++) {
            uint32_t d = arow[p] * PITCH + ac4[p] * 4;
            st[d]     = f2tf(pA[p].x); st[d + 1] = f2tf(pA[p].y);
            st[d + 2] = f2tf(pA[p].z); st[d + 3] = f2tf(pA[p].w);
        }
        uint32_t* sb = (uint32_t*)smem + OFF_B / 4;
#pragma unroll
        for (int p = 0; p < 2; p++) {
            uint32_t d = brow[p] * PITCH + bc4[p] * 4;
            sb[d]     = f2tf(pB[p].x); sb[d + 1] = f2tf(pB[p].y);
            sb[d + 2] = f2tf(pB[p].z); sb[d + 3] = f2tf(pB[p].w);
        }
    }
    __syncthreads();

    int buf = 0;
    for (int c = 0; c < NCH; c++) {
        if (c + 1 < NCH) {
            int kb = (c + 1) * GK;
#pragma unroll
            for (int p = 0; p < 4; p++)
                pA[p] = *(const float4*)(A + (size_t)(m0 + arow[p]) * INPUT + kb + ac4[p] * 4);
#pragma unroll
            for (int p = 0; p < 2; p++)
                pB[p] = *(const float4*)(W + (size_t)(n0 + brow[p]) * INPUT + kb + bc4[p] * 4);
        }

        // ---- compute on stage buf: 4 k8 steps ----
        const uint32_t* sa = (const uint32_t*)smem + buf * (STAGE_B / 4);
        const uint32_t* sb = sa + OFF_B / 4;
#pragma unroll
        for (int kk = 0; kk < 4; kk++) {
            const int kcol = kk * 8 + tg;
            uint32_t af[2][4], bf[4][2];
#pragma unroll
            for (int am = 0; am < 2; am++) {
                uint32_t r0 = (wm + am * 16 + g) * PITCH + kcol;
                af[am][0] = sa[r0];
                af[am][1] = sa[r0 + 8 * PITCH];
                af[am][2] = sa[r0 + 4];
                af[am][3] = sa[r0 + 8 * PITCH + 4];
            }
#pragma unroll
            for (int an = 0; an < 4; an++) {
                uint32_t rb = (wn + an * 8 + g) * PITCH + kcol;
                bf[an][0] = sb[rb];
                bf[an][1] = sb[rb + 4];
            }
#pragma unroll
            for (int am = 0; am < 2; am++)
#pragma unroll
                for (int an = 0; an < 4; an++)
                    mma_tf32(acc[am][an], af[am], bf[an]);
        }

        // ---- cvt + STS next chunk into other stage ----
        if (c + 1 < NCH) {
            uint32_t* st = (uint32_t*)smem + (buf ^ 1) * (STAGE_B / 4);
            uint32_t* sn = st + OFF_B / 4;
#pragma unroll
            for (int p = 0; p < 4; p++) {
                uint32_t d = arow[p] * PITCH + ac4[p] * 4;
                st[d]     = f2tf(pA[p].x); st[d + 1] = f2tf(pA[p].y);
                st[d + 2] = f2tf(pA[p].z); st[d + 3] = f2tf(pA[p].w);
            }
#pragma unroll
            for (int p = 0; p < 2; p++) {
                uint32_t d = brow[p] * PITCH + bc4[p] * 4;
                sn[d]     = f2tf(pB[p].x); sn[d + 1] = f2tf(pB[p].y);
                sn[d + 2] = f2tf(pB[p].z); sn[d + 3] = f2tf(pB[p].w);
            }
            __syncthreads();
            buf ^= 1;
        }
    }

    // ---- epilogue: add biases, store (D lane mapping identical to R10/R11) ----
#pragma unroll
    for (int am = 0; am < 2; am++) {
        int m = m0 + wm + am * 16 + g;
#pragma unroll
        for (int an = 0; an < 4; an++) {
            int n = n0 + wn + an * 8 + tg * 2;
            float bi0 = b_ih[n]     + b_hh[n];
            float bi1 = b_ih[n + 1] + b_hh[n + 1];
            float2 v0 = make_float2(acc[am][an][0] + bi0, acc[am][an][1] + bi1);
            float2 v1 = make_float2(acc[am][an][2] + bi0, acc[am][an][3] + bi1);
            *(float2*)&g_xproj[(size_t)m * GATES + n]       = v0;
            *(float2*)&g_xproj[(size_t)(m + 8) * GATES + n] = v1;
        }
    }
}

// ---------------- persistent LSTM scan: payload epochs + clock-paced poll ----------------
#define SCAN_CTAS 128

__device__ __forceinline__ float fast_sigmoid(float x) {
    return __fdividef(1.f, 1.f + __expf(-x));
}
__device__ __forceinline__ float fast_tanh(float x) {
    float e = __expf(-2.f * x);
    return __fdividef(1.f - e, 1.f + e);
}
__device__ __forceinline__ unsigned long long ld_rlx(const unsigned long long* p) {
    unsigned long long v;
    asm volatile("ld.relaxed.gpu.global.u64 %0, [%1];" : "=l"(v) : "l"(p) : "memory");
    return v;
}
__device__ __forceinline__ void st_rlx(unsigned long long* p, unsigned long long v) {
    asm volatile("st.relaxed.gpu.global.u64 [%0], %1;" :: "l"(p), "l"(v) : "memory");
}

__global__ __launch_bounds__(256, 1)
void scan_kernel(const float* __restrict__ Whh) {
    __shared__ float hs[2][HID];

    const int tid  = threadIdx.x;
    const int warp = tid >> 5;
    const int lane = tid & 31;
    const int b    = blockIdx.x;
    const int j    = b * 8 + warp;

    unsigned long long wreg[4][8][2];
#pragma unroll
    for (int g = 0; g < 4; g++) {
        const float* wrow = Whh + (size_t)(g * HID + j) * HID;
#pragma unroll
        for (int i = 0; i < 8; i++) {
            ulonglong2 v = *(const ulonglong2*)&wrow[lane * 4 + i * 128];
            wreg[g][i][0] = v.x;
            wreg[g][i][1] = v.y;
        }
    }

    float cstate = 0.f;

    for (int t = 0; t < T_STEPS; t++) {
        float xg0 = __ldg(&g_xproj[(size_t)t * GATES + 0 * HID + j]);
        float xg1 = __ldg(&g_xproj[(size_t)t * GATES + 1 * HID + j]);
        float xg2 = __ldg(&g_xproj[(size_t)t * GATES + 2 * HID + j]);
        float xg3 = __ldg(&g_xproj[(size_t)t * GATES + 3 * HID + j]);

        const unsigned long long* p0 = g_hp[t & 1] + tid;
        const unsigned int want = (unsigned int)t;
        unsigned long long v0, v1, v2, v3;
        for (;;) {
            v0 = ld_rlx(p0);
            v1 = ld_rlx(p0 + 256);
            v2 = ld_rlx(p0 + 512);
            v3 = ld_rlx(p0 + 768);
            bool ok = ((unsigned int)(v0 >> 32) == want) &
                      ((unsigned int)(v1 >> 32) == want) &
                      ((unsigned int)(v2 >> 32) == want) &
                      ((unsigned int)(v3 >> 32) == want);
            if (ok) break;
            // clock-gated pause (~200 cyc, zero memory traffic) so the
            // L1tex/LTS queues drain instead of being flooded by spin LDGs
            long long tgt = clock64() + 200;
            while (clock64() < tgt) { }
        }
        float* cur = hs[t & 1];
        cur[tid]       = __uint_as_float((unsigned int)v0);
        cur[tid + 256] = __uint_as_float((unsigned int)v1);
        cur[tid + 512] = __uint_as_float((unsigned int)v2);
        cur[tid + 768] = __uint_as_float((unsigned int)v3);
        __syncthreads();

        unsigned long long acc[4] = {0ULL, 0ULL, 0ULL, 0ULL};
#pragma unroll
        for (int i = 0; i < 8; i++) {
            ulonglong2 h2 = *(const ulonglong2*)&cur[lane * 4 + i * 128];
#pragma unroll
            for (int g = 0; g < 4; g++) {
                ffma2(acc[g], h2.x, wreg[g][i][0]);
                ffma2(acc[g], h2.y, wreg[g][i][1]);
            }
        }

        float red[4];
#pragma unroll
        for (int g = 0; g < 4; g++) {
            float lo, hi;
            unpack2(acc[g], lo, hi);
            red[g] = lo + hi;
        }
#pragma unroll
        for (int o = 16; o; o >>= 1) {
#pragma unroll
            for (int g = 0; g < 4; g++)
                red[g] += __shfl_xor_sync(0xffffffffu, red[g], o);
        }

        float gi = fast_sigmoid(xg0 + red[0]);
        float gf = fast_sigmoid(xg1 + red[1]);
        float gg = fast_tanh(xg2 + red[2]);
        float go = fast_sigmoid(xg3 + red[3]);
        cstate = gf * cstate + gi * gg;
        float hnew = go * fast_tanh(cstate);

        if (lane == 0) {
            unsigned long long pk =
                ((unsigned long long)(unsigned int)(t + 1) << 32) |
                (unsigned long long)__float_as_uint(hnew);
            st_rlx(&g_hp[(t + 1) & 1][j], pk);
        }
    }
}

// ---------------- final: out = h_T @ fc_w^T + fc_b ----------------
__global__ __launch_bounds__(256, 2)
void final_kernel(const float* __restrict__ fcw,
                  const float* __restrict__ fcb,
                  float* __restrict__ out) {
    __shared__ float hs[HID];
    const int tid = threadIdx.x, warp = tid >> 5, lane = tid & 31;
#pragma unroll
    for (int q = 0; q < 4; q++)
        hs[tid + q * 256] = __uint_as_float((unsigned int)g_hp[0][tid + q * 256]);
    __syncthreads();

    int row = blockIdx.x * 16 + warp * 2;
    const float* wr0 = fcw + (size_t)row * HID;
    const float* wr1 = wr0 + HID;
    float acc0 = 0.f, acc1 = 0.f;
#pragma unroll
    for (int i = 0; i < 8; i++) {
        float4 h4 = *(const float4*)&hs[lane * 4 + i * 128];
        float4 a4 = *(const float4*)&wr0[lane * 4 + i * 128];
        float4 b4 = *(const float4*)&wr1[lane * 4 + i * 128];
        acc0 += a4.x * h4.x + a4.y * h4.y + a4.z * h4.z + a4.w * h4.w;
        acc1 += b4.x * h4.x + b4.y * h4.y + b4.z * h4.z + b4.w * h4.w;
    }
#pragma unroll
    for (int o = 16; o; o >>= 1) {
        acc0 += __shfl_xor_sync(0xffffffffu, acc0, o);
        acc1 += __shfl_xor_sync(0xffffffffu, acc1, o);
    }
    if (lane == 0) {
        out[row]     = acc0 + fcb[row];
        out[row + 1] = acc1 + fcb[row + 1];
    }
}

// ---------------- launch ----------------
extern "C" void kernel_launch(void* const* d_in, const int* in_sizes, int n_in,
                              void* d_out, int out_size) {
    const float* frames = (const float*)d_in[0];
    const float* W_ih   = (const float*)d_in[1];
    const float* W_hh   = (const float*)d_in[2];
    const float* b_ih   = (const float*)d_in[3];
    const float* b_hh   = (const float*)d_in[4];
    const float* fc_w   = (const float*)d_in[5];
    const float* fc_b   = (const float*)d_in[6];
    float* out = (float*)d_out;

    cudaFuncSetAttribute(gemm_tf32_kernel,
                         cudaFuncAttributeMaxDynamicSharedMemorySize, GEMM_SMEM);

    init_kernel<<<4, 256>>>();

    dim3 gg(GATES / 64, T_STEPS / 128);   // (64, 2) = 128 CTAs
    gemm_tf32_kernel<<<gg, 256, GEMM_SMEM>>>(frames, W_ih, b_ih, b_hh);

    scan_kernel<<<SCAN_CTAS, 256>>>(W_hh);

    final_kernel<<<12288 / 16, 256>>>(fc_w, fc_b, out);
}